// round 15
// baseline (speedup 1.0000x reference)
#include <cuda_runtime.h>
#include <cuda_bf16.h>
#include <mma.h>
#include <math.h>
#include <stdint.h>

using namespace nvcuda;

#define BS 4
#define NQ 6000
#define NV 13294
#define EMB 256
#define NH 8
#define HD 32

#define MV (BS * NV)          // 53176
#define MQ (BS * NQ)          // 24000
#define MV_PAD 53248          // 416 * 128
#define MQ_PAD 24064          // 188 * 128

// tile counts for the batched input GEMM
#define T_VAL 832             // (MV_PAD/128) * 2
#define T_OFF 376             // (MQ_PAD/128) * 2
#define T_AW  188             // (MQ_PAD/128) * 1
#define T_ALL (T_VAL + T_OFF + T_AW)   // 1396

// Scratch (device globals: allocation-free per harness rules).
__device__ __nv_bfloat16 g_wv  [256 * 256];             // W_val  bf16 [K][N]
__device__ __nv_bfloat16 g_wof [256 * 256];             // W_off  bf16 [K][N]
__device__ __nv_bfloat16 g_wat [256 * 128];             // W_attn bf16 [K][N]
__device__ __nv_bfloat16 g_wo  [256 * 256];             // W_out  bf16 [K][N]
__device__ __nv_bfloat16 g_vb  [(size_t)NH * MV_PAD * HD];  // value proj, HEAD-MAJOR [h][pix][32]
__device__ float         g_off [(size_t)MQ_PAD * 256];  // sampling offsets
__device__ float         g_aw  [(size_t)MQ_PAD * 128];  // attn logits
__device__ __nv_bfloat16 g_mid [(size_t)MQ_PAD * 256];  // aggregated heads (bf16)
__device__ float         g_brep[4 * 16 * 256];          // 16-row-replicated bias tiles

// ---------------------------------------------------------------------------
// Small conversion pass: WEIGHTS f32->bf16 (row-major [K][N]) + bias tiles.
// Segments (float4): Wv 16384, Wof 16384, Wat 8192, Wo 16384, brep 4096.
// ---------------------------------------------------------------------------
#define S_W   16384
#define S_WA  8192
#define S_WTOT (3 * S_W + S_WA)
#define S_TOTW (S_WTOT + 4096)

__global__ void cvt_w(const float* __restrict__ Wv, const float* __restrict__ Wof,
                      const float* __restrict__ Wat, const float* __restrict__ Wo,
                      const float* __restrict__ b0, const float* __restrict__ b1,
                      const float* __restrict__ b2, const float* __restrict__ b3)
{
    int i = blockIdx.x * blockDim.x + threadIdx.x;
    if (i >= S_TOTW) return;
    if (i >= S_WTOT) {               // replicated bias tiles (f32)
        int j = i - S_WTOT;          // [0, 4096)
        int t = j >> 10;
        int c4 = j & 63;
        const float* b = (t == 0) ? b0 : (t == 1) ? b1 : (t == 2) ? b2 : b3;
        int col4 = (t == 2) ? (c4 & 31) : c4;
        ((float4*)g_brep)[j] = ((const float4*)b)[col4];
        return;
    }
    const float* src; __nv_bfloat16* dst;
    int j = i;
    if (j < S_W)             { src = Wv;  dst = g_wv; }
    else if (j < 2 * S_W)    { j -= S_W;     src = Wof; dst = g_wof; }
    else if (j < 2*S_W+S_WA) { j -= 2 * S_W; src = Wat; dst = g_wat; }
    else                     { j -= 2 * S_W + S_WA; src = Wo; dst = g_wo; }
    float4 v = ((const float4*)src)[j];
    __nv_bfloat162 t0 = __floats2bfloat162_rn(v.x, v.y);
    __nv_bfloat162 t1 = __floats2bfloat162_rn(v.z, v.w);
    uint2 o; o.x = *(uint32_t*)&t0; o.y = *(uint32_t*)&t1;
    ((uint2*)dst)[j] = o;
}

// ---------------------------------------------------------------------------
// bf16 tensor-core GEMM core (wmma m16n16k16), 128x128 tile, 256 threads,
// 8 warps (4x2), warp tile 32x64, BK=32.
// Two mainloops:
//   mainloop<8>     : A already bf16, 4-stage cp.async for A+B (gemm_out)
//   mainloop_cvt<8> : A is f32 in GMEM; LDG.128 + convert + STS (2-stage A),
//                     B via 4-stage cp.async (gemm_batched)
// ---------------------------------------------------------------------------
#define AROW 40                    // A smem row stride (bf16)
#define BROW 136                   // B smem row stride
#define A_ST (128 * AROW)          // 5120 bf16 per A stage
#define B_ST (32 * BROW)           // 4352 bf16 per B stage
#define NSTG 4
#define GEMM_SMEM (NSTG * (A_ST + B_ST) * 2)   // 75776 bytes

__device__ __forceinline__ void cp16(void* dst_smem, const void* src, int src_bytes)
{
    uint32_t d = (uint32_t)__cvta_generic_to_shared(dst_smem);
    asm volatile("cp.async.cg.shared.global [%0], [%1], 16, %2;\n"
                 :: "r"(d), "l"(src), "r"(src_bytes));
}
template<int N> __device__ __forceinline__ void cpwait()
{
    asm volatile("cp.async.wait_group %0;\n" :: "n"(N));
}
__device__ __forceinline__ uint2 pack4(float4 v)
{
    __nv_bfloat162 lo = __floats2bfloat162_rn(v.x, v.y);
    __nv_bfloat162 hi = __floats2bfloat162_rn(v.z, v.w);
    uint2 o; o.x = *(uint32_t*)&lo; o.y = *(uint32_t*)&hi;
    return o;
}

struct GemmCore {
    __nv_bfloat16* As; __nv_bfloat16* Bsm;
    int tid, lane, wid, warp_m, warp_n, row0, col0;
    wmma::fragment<wmma::accumulator, 16, 16, 16, float> acc[2][4];

    __device__ __forceinline__ void init(char* sm, int r0, int c0, const float* brep)
    {
        As = (__nv_bfloat16*)sm; Bsm = As + NSTG * A_ST;
        tid = threadIdx.x; lane = tid & 31; wid = tid >> 5;
        warp_m = wid >> 1; warp_n = wid & 1;
        row0 = r0; col0 = c0;
#pragma unroll
        for (int i = 0; i < 2; i++)
#pragma unroll
            for (int j = 0; j < 4; j++)
                wmma::load_matrix_sync(acc[i][j],
                    brep + col0 + warp_n * 64 + j * 16, 256, wmma::mem_row_major);
    }

    // --- bf16-A path (gemm_out): A+B one cp.async group per stage ---
    __device__ __forceinline__ void prefetch(const __nv_bfloat16* A, const __nv_bfloat16* B,
                                             int M, int N, int K, int k0, int st)
    {
        const int am = tid >> 2, ac = tid & 3;
        const int bk = tid >> 4, bc = tid & 15;
#pragma unroll
        for (int it = 0; it < 2; it++) {
            int m = am + it * 64;
            int r = row0 + m;
            cp16(&As[st * A_ST + m * AROW + ac * 8],
                 A + (size_t)r * K + k0 + ac * 8, (r < M) ? 16 : 0);
        }
#pragma unroll
        for (int it = 0; it < 2; it++) {
            int k = bk + it * 16;
            cp16(&Bsm[st * B_ST + k * BROW + bc * 8],
                 B + (size_t)(k0 + k) * N + col0 + bc * 8, 16);
        }
        asm volatile("cp.async.commit_group;\n");
    }

    // --- B-only cp.async stage (cvt-A path) ---
    __device__ __forceinline__ void prefetchB(const __nv_bfloat16* B, int N, int k0, int st)
    {
        const int bk = tid >> 4, bc = tid & 15;
#pragma unroll
        for (int it = 0; it < 2; it++) {
            int k = bk + it * 16;
            cp16(&Bsm[st * B_ST + k * BROW + bc * 8],
                 B + (size_t)(k0 + k) * N + col0 + bc * 8, 16);
        }
        asm volatile("cp.async.commit_group;\n");
    }

    // --- f32 A tile load + convert: thread t -> row t/2, half t&1 (16 floats) ---
    __device__ __forceinline__ void ldgA_cvt(const float* A, int M, int k0, uint2* areg)
    {
        const int r = row0 + (tid >> 1);
        const float4* src = (const float4*)(A + (size_t)r * 256 + k0 + (tid & 1) * 16);
        if (r < M) {
#pragma unroll
            for (int q = 0; q < 4; q++) areg[q] = pack4(src[q]);
        } else {
#pragma unroll
            for (int q = 0; q < 4; q++) areg[q] = make_uint2(0u, 0u);
        }
    }
    __device__ __forceinline__ void stsA(const uint2* areg, int st)
    {
        __nv_bfloat16* dst = As + st * A_ST + (tid >> 1) * AROW + (tid & 1) * 16;
        uint4 w0; w0.x = areg[0].x; w0.y = areg[0].y; w0.z = areg[1].x; w0.w = areg[1].y;
        uint4 w1; w1.x = areg[2].x; w1.y = areg[2].y; w1.z = areg[3].x; w1.w = areg[3].y;
        *(uint4*)dst = w0;
        *(uint4*)(dst + 8) = w1;
    }

    __device__ __forceinline__ void compute_stage2(int ast, int bst)
    {
        const __nv_bfloat16* as = As + ast * A_ST;
        const __nv_bfloat16* bs = Bsm + bst * B_ST;
#pragma unroll
        for (int kk = 0; kk < 2; kk++) {
            wmma::fragment<wmma::matrix_a, 16, 16, 16, __nv_bfloat16, wmma::row_major> a[2];
            wmma::fragment<wmma::matrix_b, 16, 16, 16, __nv_bfloat16, wmma::row_major> b[4];
#pragma unroll
            for (int ii = 0; ii < 2; ii++)
                wmma::load_matrix_sync(a[ii], as + (warp_m * 32 + ii * 16) * AROW + kk * 16, AROW);
#pragma unroll
            for (int j = 0; j < 4; j++)
                wmma::load_matrix_sync(b[j], bs + (kk * 16) * BROW + warp_n * 64 + j * 16, BROW);
#pragma unroll
            for (int ii = 0; ii < 2; ii++)
#pragma unroll
                for (int j = 0; j < 4; j++)
                    wmma::mma_sync(acc[ii][j], a[ii], b[j], acc[ii][j]);
        }
    }

    template<int ITERS>
    __device__ __forceinline__ void mainloop(const __nv_bfloat16* A, const __nv_bfloat16* B,
                                             int M, int N, int K)
    {
        prefetch(A, B, M, N, K, 0,  0);
        prefetch(A, B, M, N, K, 32, 1);
        prefetch(A, B, M, N, K, 64, 2);
#pragma unroll
        for (int i = 0; i < ITERS; i++) {
            if (i < ITERS - 2)       cpwait<2>();
            else if (i == ITERS - 2) cpwait<1>();
            else                     cpwait<0>();
            __syncthreads();
            if (i + 3 < ITERS)
                prefetch(A, B, M, N, K, (i + 3) * 32, (i + 3) & 3);
            compute_stage2(i & 3, i & 3);
        }
    }

    // A = f32 in GMEM (converted in-flight). 2-stage A (smem), 4-stage B.
    template<int ITERS>
    __device__ __forceinline__ void mainloop_cvt(const float* A, const __nv_bfloat16* B,
                                                 int M, int N)
    {
        uint2 areg[4];
        ldgA_cvt(A, M, 0, areg);
        prefetchB(B, N, 0,  0);
        prefetchB(B, N, 32, 1);
        prefetchB(B, N, 64, 2);
#pragma unroll
        for (int i = 0; i < ITERS; i++) {
            __syncthreads();                       // A-stage (i&1) free; B stage writable
            stsA(areg, i & 1);
            if (i + 3 < ITERS)
                prefetchB(B, N, (i + 3) * 32, (i + 3) & 3);
            if (i + 1 < ITERS)
                ldgA_cvt(A, M, (i + 1) * 32, areg);
            if (i <= ITERS - 4)      cpwait<3>();
            else if (i == ITERS - 3) cpwait<2>();
            else if (i == ITERS - 2) cpwait<1>();
            else                     cpwait<0>();
            __syncthreads();                       // STS + cp.async visible
            compute_stage2(i & 1, i & 3);
        }
    }

    // Staged f32 epilogue: accumulators -> 128x128 smem -> coalesced float4
    // writes (+ optional coalesced residual).
    __device__ __forceinline__ void store_f32_staged(float* C, const float* resid,
                                                     int N, int Mstore, char* sm)
    {
        float* buf = (float*)sm;
        __syncthreads();
#pragma unroll
        for (int i = 0; i < 2; i++)
#pragma unroll
            for (int j = 0; j < 4; j++)
                wmma::store_matrix_sync(
                    buf + (warp_m * 32 + i * 16) * 128 + warp_n * 64 + j * 16,
                    acc[i][j], 128, wmma::mem_row_major);
        __syncthreads();
#pragma unroll
        for (int k = tid; k < 128 * 32; k += 256) {
            int r = k >> 5, c4 = k & 31;
            int gr = row0 + r;
            if (gr >= Mstore) continue;
            float4 v = ((const float4*)buf)[k];
            if (resid) {
                float4 rv = ((const float4*)(resid + (size_t)gr * N + col0))[c4];
                v.x += rv.x; v.y += rv.y; v.z += rv.z; v.w += rv.w;
            }
            ((float4*)(C + (size_t)gr * N + col0))[c4] = v;
        }
    }

    // bf16 epilogue, HEAD-MAJOR scatter for the value projection.
    __device__ __forceinline__ void store_bf16_hm(__nv_bfloat16* Cb, char* sm)
    {
        float* scratch = (float*)sm + wid * 256;
        __syncthreads();
#pragma unroll
        for (int i = 0; i < 2; i++)
#pragma unroll
            for (int j = 0; j < 4; j++) {
                __syncwarp();
                wmma::store_matrix_sync(scratch, acc[i][j], 16, wmma::mem_row_major);
                __syncwarp();
                int r = lane >> 1, cb = (lane & 1) * 8;
                const float* sp = scratch + r * 16 + cb;
                float4 f0 = *(const float4*)sp;
                float4 f1 = *(const float4*)(sp + 4);
                uint4 o;
                __nv_bfloat162 t0 = __floats2bfloat162_rn(f0.x, f0.y);
                __nv_bfloat162 t1 = __floats2bfloat162_rn(f0.z, f0.w);
                __nv_bfloat162 t2 = __floats2bfloat162_rn(f1.x, f1.y);
                __nv_bfloat162 t3 = __floats2bfloat162_rn(f1.z, f1.w);
                o.x = *(uint32_t*)&t0; o.y = *(uint32_t*)&t1;
                o.z = *(uint32_t*)&t2; o.w = *(uint32_t*)&t3;
                int grow = row0 + warp_m * 32 + i * 16 + r;
                int gcol = col0 + warp_n * 64 + j * 16 + cb;
                size_t off = (size_t)(gcol >> 5) * (MV_PAD * HD) + (size_t)grow * HD + (gcol & 31);
                *(uint4*)(Cb + off) = o;
            }
    }
};

// ---------------------------------------------------------------------------
// Batched input GEMM: A read directly from f32 inputs (fused conversion).
//   tiles [0, 832):     g_vb  = value @ W_val + b_val  (bf16 head-major)
//   tiles [832, 1208):  g_off = query @ W_off + b_off  (f32)
//   tiles [1208, 1396): g_aw  = query @ W_attn + b_attn (f32, N=128)
// ---------------------------------------------------------------------------
__global__ __launch_bounds__(256, 2)
void gemm_batched(const float* __restrict__ value, const float* __restrict__ query,
                  const float* __restrict__ brep)
{
    extern __shared__ char smc[];
    int t = blockIdx.x;

    const float* A;
    const __nv_bfloat16* B;
    const float* brp;
    int M, N, row_t, col_t, prob;
    if (t < T_VAL) {
        prob = 0; A = value; B = g_wv; brp = brep;
        M = MV; N = 256; row_t = t >> 1; col_t = t & 1;
    } else if (t < T_VAL + T_OFF) {
        int u = t - T_VAL;
        prob = 1; A = query; B = g_wof; brp = brep + 4096;
        M = MQ; N = 256; row_t = u >> 1; col_t = u & 1;
    } else {
        int u = t - T_VAL - T_OFF;
        prob = 2; A = query; B = g_wat; brp = brep + 2 * 4096;
        M = MQ; N = 128; row_t = u; col_t = 0;
    }

    GemmCore g;
    g.init(smc, row_t * 128, col_t * 128, brp);
    g.mainloop_cvt<8>(A, B, M, N);

    if (prob == 0)       g.store_bf16_hm(g_vb, smc);
    else if (prob == 1)  g.store_f32_staged(g_off, nullptr, 256, MQ_PAD, smc);
    else                 g.store_f32_staged(g_aw,  nullptr, 128, MQ_PAD, smc);
}

// ---------------------------------------------------------------------------
// Output projection + bias + fp32 residual (A = bf16 g_mid)
// ---------------------------------------------------------------------------
__global__ __launch_bounds__(256, 2)
void gemm_out(const float* __restrict__ brep, const float* __restrict__ query,
              float* __restrict__ out)
{
    extern __shared__ char smc[];
    GemmCore g;
    g.init(smc, blockIdx.y * 128, blockIdx.x * 128, brep + 3 * 4096);
    g.mainloop<8>(g_mid, g_wo, MQ, 256, 256);
    g.store_f32_staged(out, query, 256, MQ, smc);
}

// ---------------------------------------------------------------------------
// Fused sampling: TWO (b,q,h) units per warp (16 lanes each). Unchanged.
// ---------------------------------------------------------------------------
#define HSTRIDE (MV_PAD * HD)

__global__ __launch_bounds__(256)
void sample_fused(const float* __restrict__ refp)
{
    __shared__ int2 meta[16][66];

    const int warp = (blockIdx.x * blockDim.x + threadIdx.x) >> 5;
    const int lane = threadIdx.x & 31;
    const int half = lane >> 4;
    const int unit = warp * 2 + half;
    const int uloc = (threadIdx.x >> 5) * 2 + half;

    const int h  = unit & 7;
    const int bq = unit >> 3;
    const int b  = bq / NQ;

    {
        const int p = lane & 15;
        const float* awp = g_aw + bq * 128 + h * 16;
        float a = awp[p];
        float m = a;
#pragma unroll
        for (int o = 8; o; o >>= 1) m = fmaxf(m, __shfl_xor_sync(0xffffffffu, m, o));
        float e = __expf(a - m);
        float s = e;
#pragma unroll
        for (int o = 8; o; o >>= 1) s += __shfl_xor_sync(0xffffffffu, s, o);
        const float wp = e / s;

        const int l = p >> 2;
        const int W = (0x0D193264 >> (l * 8)) & 0xFF;               // 100,50,25,13
        const long long spack = 0LL | (10000LL << 14) | (12500LL << 28) | (13125LL << 42);
        const int START = (int)((spack >> (14 * l)) & 0x3FFF);      // 0,10000,12500,13125

        const float* offp = g_off + bq * 256 + h * 32;
        float rx = refp[bq * 8 + 2 * l];
        float ry = refp[bq * 8 + 2 * l + 1];

        float x = fmaf(rx, (float)W, offp[2 * p]) - 0.5f;
        float y = fmaf(ry, (float)W, offp[2 * p + 1]) - 0.5f;
        float xf = floorf(x), yf = floorf(y);
        int   x0 = (int)xf,  y0 = (int)yf;
        float wx1 = x - xf, wy1 = y - yf;
        float wx0 = 1.f - wx1, wy0 = 1.f - wy1;

        wx0 *= (float)(x0 >= 0 && x0 < W);
        wx1 *= (float)(x0 >= -1 && x0 < W - 1);
        wy0 *= (float)(y0 >= 0 && y0 < W);
        wy1 *= (float)(y0 >= -1 && y0 < W - 1);

        int xc0 = min(max(x0, 0), W - 1);
        int xc1 = min(max(x0 + 1, 0), W - 1);
        int yc0 = min(max(y0, 0), W - 1);
        int yc1 = min(max(y0 + 1, 0), W - 1);

        const int hb   = h * HSTRIDE;
        const int base = b * NV + START;
        int r0 = hb + (base + yc0 * W) * HD;
        int r1 = hb + (base + yc1 * W) * HD;

        int2* mp = &meta[uloc][p * 4];
        *(int4*)(mp)     = make_int4(r0 + xc0 * HD, __float_as_int(wp * wy0 * wx0),
                                     r0 + xc1 * HD, __float_as_int(wp * wy0 * wx1));
        *(int4*)(mp + 2) = make_int4(r1 + xc0 * HD, __float_as_int(wp * wy1 * wx0),
                                     r1 + xc1 * HD, __float_as_int(wp * wy1 * wx1));
    }
    __syncwarp();

    const int corner = (lane >> 2) & 3;
    const int sub    = lane & 3;
    const __nv_bfloat16* vbp = g_vb + sub * 8;
    const int2* mrow = &meta[uloc][corner];

    float a0 = 0.f, a1 = 0.f, a2 = 0.f, a3 = 0.f, a4 = 0.f, a5 = 0.f, a6 = 0.f, a7 = 0.f;
#pragma unroll
    for (int pt = 0; pt < 16; pt++) {
        int2 md = mrow[pt * 4];
        float w = __int_as_float(md.y);
        uint4 raw = *(const uint4*)(vbp + md.x);
        float2 f0 = __bfloat1622float2(*(__nv_bfloat162*)&raw.x);
        float2 f1 = __bfloat1622float2(*(__nv_bfloat162*)&raw.y);
        float2 f2 = __bfloat1622float2(*(__nv_bfloat162*)&raw.z);
        float2 f3 = __bfloat1622float2(*(__nv_bfloat162*)&raw.w);
        a0 = fmaf(w, f0.x, a0); a1 = fmaf(w, f0.y, a1);
        a2 = fmaf(w, f1.x, a2); a3 = fmaf(w, f1.y, a3);
        a4 = fmaf(w, f2.x, a4); a5 = fmaf(w, f2.y, a5);
        a6 = fmaf(w, f3.x, a6); a7 = fmaf(w, f3.y, a7);
    }
#pragma unroll
    for (int o = 4; o <= 8; o <<= 1) {
        a0 += __shfl_xor_sync(0xffffffffu, a0, o);
        a1 += __shfl_xor_sync(0xffffffffu, a1, o);
        a2 += __shfl_xor_sync(0xffffffffu, a2, o);
        a3 += __shfl_xor_sync(0xffffffffu, a3, o);
        a4 += __shfl_xor_sync(0xffffffffu, a4, o);
        a5 += __shfl_xor_sync(0xffffffffu, a5, o);
        a6 += __shfl_xor_sync(0xffffffffu, a6, o);
        a7 += __shfl_xor_sync(0xffffffffu, a7, o);
    }
    if (corner == 0) {
        __nv_bfloat162 t0 = __floats2bfloat162_rn(a0, a1);
        __nv_bfloat162 t1 = __floats2bfloat162_rn(a2, a3);
        __nv_bfloat162 t2 = __floats2bfloat162_rn(a4, a5);
        __nv_bfloat162 t3 = __floats2bfloat162_rn(a6, a7);
        uint4 o;
        o.x = *(uint32_t*)&t0; o.y = *(uint32_t*)&t1;
        o.z = *(uint32_t*)&t2; o.w = *(uint32_t*)&t3;
        *(uint4*)&g_mid[bq * 256 + h * HD + sub * 8] = o;
    }
}

// ---------------------------------------------------------------------------
extern "C" void kernel_launch(void* const* d_in, const int* in_sizes, int n_in,
                              void* d_out, int out_size)
{
    const float* query  = (const float*)d_in[0];
    const float* value  = (const float*)d_in[1];
    const float* refp   = (const float*)d_in[2];
    const float* W_off  = (const float*)d_in[3];
    const float* b_off  = (const float*)d_in[4];
    const float* W_attn = (const float*)d_in[5];
    const float* b_attn = (const float*)d_in[6];
    const float* W_val  = (const float*)d_in[7];
    const float* b_val  = (const float*)d_in[8];
    const float* W_out  = (const float*)d_in[9];
    const float* b_out  = (const float*)d_in[10];
    float* out = (float*)d_out;

    float* pbrep;
    cudaGetSymbolAddress((void**)&pbrep, g_brep);

    cudaFuncSetAttribute(gemm_batched, cudaFuncAttributeMaxDynamicSharedMemorySize, GEMM_SMEM);
    cudaFuncSetAttribute(gemm_out,     cudaFuncAttributeMaxDynamicSharedMemorySize, GEMM_SMEM);

    // 0) small weight/bias conversion (value/query conversion is fused into GEMM)
    cvt_w<<<(S_TOTW + 255) / 256, 256>>>(W_val, W_off, W_attn, W_out,
                                         b_val, b_off, b_attn, b_out);

    // 1) all three input projections, A converted in-flight
    gemm_batched<<<T_ALL, 256, GEMM_SMEM>>>(value, query, pbrep);

    // 2) fused sampler: 2 units/warp, head-major gather
    sample_fused<<<(MQ * NH) / 16, 256>>>(refp);

    // 3) output projection + bias + fp32 residual
    gemm_out<<<dim3(2, MQ_PAD / 128), 256, GEMM_SMEM>>>(pbrep, query, out);
}

// round 16
// speedup vs baseline: 1.0461x; 1.0461x over previous
#include <cuda_runtime.h>
#include <cuda_bf16.h>
#include <mma.h>
#include <math.h>
#include <stdint.h>

using namespace nvcuda;

#define BS 4
#define NQ 6000
#define NV 13294
#define EMB 256
#define NH 8
#define HD 32

#define MV (BS * NV)          // 53176
#define MQ (BS * NQ)          // 24000
#define MV_PAD 53248          // 416 * 128
#define MQ_PAD 24064          // 188 * 128

#define T_VALV 416            // value-proj CTAs (128x256 tiles)
#define T_OFF 376             // (MQ_PAD/128) * 2
#define T_AW  188             // (MQ_PAD/128) * 1
#define T_QP  (T_OFF + T_AW)  // 564

// Scratch (device globals: allocation-free per harness rules).
__device__ __nv_bfloat16 g_qb  [(size_t)MQ_PAD * EMB];  // query, bf16
__device__ __nv_bfloat16 g_wv  [256 * 256];             // W_val  bf16 [K][N]
__device__ __nv_bfloat16 g_wof [256 * 256];             // W_off  bf16 [K][N]
__device__ __nv_bfloat16 g_wat [256 * 128];             // W_attn bf16 [K][N]
__device__ __nv_bfloat16 g_wo  [256 * 256];             // W_out  bf16 [K][N]
__device__ __nv_bfloat16 g_vb  [(size_t)NH * MV_PAD * HD];  // value proj, HEAD-MAJOR [h][pix][32]
__device__ float         g_off [(size_t)MQ_PAD * 256];  // sampling offsets
__device__ float         g_aw  [(size_t)MQ_PAD * 128];  // attn logits
__device__ __nv_bfloat16 g_mid [(size_t)MQ_PAD * 256];  // aggregated heads (bf16)
__device__ float         g_brep[4 * 16 * 256];          // 16-row-replicated bias tiles

// ---------------------------------------------------------------------------
// Conversion: query f32->bf16, weights f32->bf16, replicated bias tiles.
// (value conversion is fused into the value GEMM.)
// ---------------------------------------------------------------------------
#define S_QRY (MQ * 64)
#define S_W   16384
#define S_WA  8192
#define S_CVT (S_QRY + 3 * S_W + S_WA)
#define S_TOT (S_CVT + 4096)

__global__ void cvt_all(const float* __restrict__ query,
                        const float* __restrict__ Wv, const float* __restrict__ Wof,
                        const float* __restrict__ Wat, const float* __restrict__ Wo,
                        const float* __restrict__ b0, const float* __restrict__ b1,
                        const float* __restrict__ b2, const float* __restrict__ b3)
{
    int i = blockIdx.x * blockDim.x + threadIdx.x;
    if (i >= S_TOT) return;
    if (i >= S_CVT) {                 // bias tile segment (stays f32)
        int j = i - S_CVT;
        int t = j >> 10;
        int c4 = j & 63;
        const float* b = (t == 0) ? b0 : (t == 1) ? b1 : (t == 2) ? b2 : b3;
        int col4 = (t == 2) ? (c4 & 31) : c4;
        ((float4*)g_brep)[j] = ((const float4*)b)[col4];
        return;
    }
    const float* src; __nv_bfloat16* dst;
    int j = i;
    if (j < S_QRY) { src = query; dst = g_qb; }
    else { j -= S_QRY;
        if (j < S_W) { src = Wv; dst = g_wv; }
        else { j -= S_W;
            if (j < S_W) { src = Wof; dst = g_wof; }
            else { j -= S_W;
                if (j < S_WA) { src = Wat; dst = g_wat; }
                else { j -= S_WA; src = Wo; dst = g_wo; } } } }
    float4 v = ((const float4*)src)[j];
    __nv_bfloat162 t0 = __floats2bfloat162_rn(v.x, v.y);
    __nv_bfloat162 t1 = __floats2bfloat162_rn(v.z, v.w);
    uint2 o; o.x = *(uint32_t*)&t0; o.y = *(uint32_t*)&t1;
    ((uint2*)dst)[j] = o;
}

// ---------------------------------------------------------------------------
// Common helpers
// ---------------------------------------------------------------------------
__device__ __forceinline__ void cp16(void* dst_smem, const void* src, int src_bytes)
{
    uint32_t d = (uint32_t)__cvta_generic_to_shared(dst_smem);
    asm volatile("cp.async.cg.shared.global [%0], [%1], 16, %2;\n"
                 :: "r"(d), "l"(src), "r"(src_bytes));
}
template<int N> __device__ __forceinline__ void cpwait()
{
    asm volatile("cp.async.wait_group %0;\n" :: "n"(N));
}
__device__ __forceinline__ uint2 pack4(float4 v)
{
    __nv_bfloat162 lo = __floats2bfloat162_rn(v.x, v.y);
    __nv_bfloat162 hi = __floats2bfloat162_rn(v.z, v.w);
    uint2 o; o.x = *(uint32_t*)&lo; o.y = *(uint32_t*)&hi;
    return o;
}

// ---------------------------------------------------------------------------
// R11 GEMM core (256 threads, 8 warps 4x2, tile 128x128, BK=32, 4-stage).
// ---------------------------------------------------------------------------
#define AROW 40
#define BROW 136
#define A_ST (128 * AROW)
#define B_ST (32 * BROW)
#define NSTG 4
#define GEMM_SMEM (NSTG * (A_ST + B_ST) * 2)   // 75776 bytes

struct GemmCore {
    __nv_bfloat16* As; __nv_bfloat16* Bsm;
    int tid, lane, wid, warp_m, warp_n, row0, col0;
    wmma::fragment<wmma::accumulator, 16, 16, 16, float> acc[2][4];

    __device__ __forceinline__ void init(char* sm, int r0, int c0, const float* brep)
    {
        As = (__nv_bfloat16*)sm; Bsm = As + NSTG * A_ST;
        tid = threadIdx.x; lane = tid & 31; wid = tid >> 5;
        warp_m = wid >> 1; warp_n = wid & 1;
        row0 = r0; col0 = c0;
#pragma unroll
        for (int i = 0; i < 2; i++)
#pragma unroll
            for (int j = 0; j < 4; j++)
                wmma::load_matrix_sync(acc[i][j],
                    brep + col0 + warp_n * 64 + j * 16, 256, wmma::mem_row_major);
    }

    __device__ __forceinline__ void prefetch(const __nv_bfloat16* A, const __nv_bfloat16* B,
                                             int M, int N, int K, int k0, int st)
    {
        const int am = tid >> 2, ac = tid & 3;
        const int bk = tid >> 4, bc = tid & 15;
#pragma unroll
        for (int it = 0; it < 2; it++) {
            int m = am + it * 64;
            int r = row0 + m;
            cp16(&As[st * A_ST + m * AROW + ac * 8],
                 A + (size_t)r * K + k0 + ac * 8, (r < M) ? 16 : 0);
        }
#pragma unroll
        for (int it = 0; it < 2; it++) {
            int k = bk + it * 16;
            cp16(&Bsm[st * B_ST + k * BROW + bc * 8],
                 B + (size_t)(k0 + k) * N + col0 + bc * 8, 16);
        }
        asm volatile("cp.async.commit_group;\n");
    }

    __device__ __forceinline__ void compute_stage(int st)
    {
        const __nv_bfloat16* as = As + st * A_ST;
        const __nv_bfloat16* bs = Bsm + st * B_ST;
#pragma unroll
        for (int kk = 0; kk < 2; kk++) {
            wmma::fragment<wmma::matrix_a, 16, 16, 16, __nv_bfloat16, wmma::row_major> a[2];
            wmma::fragment<wmma::matrix_b, 16, 16, 16, __nv_bfloat16, wmma::row_major> b[4];
#pragma unroll
            for (int ii = 0; ii < 2; ii++)
                wmma::load_matrix_sync(a[ii], as + (warp_m * 32 + ii * 16) * AROW + kk * 16, AROW);
#pragma unroll
            for (int j = 0; j < 4; j++)
                wmma::load_matrix_sync(b[j], bs + (kk * 16) * BROW + warp_n * 64 + j * 16, BROW);
#pragma unroll
            for (int ii = 0; ii < 2; ii++)
#pragma unroll
                for (int j = 0; j < 4; j++)
                    wmma::mma_sync(acc[ii][j], a[ii], b[j], acc[ii][j]);
        }
    }

    template<int ITERS>
    __device__ __forceinline__ void mainloop(const __nv_bfloat16* A, const __nv_bfloat16* B,
                                             int M, int N, int K)
    {
        prefetch(A, B, M, N, K, 0,  0);
        prefetch(A, B, M, N, K, 32, 1);
        prefetch(A, B, M, N, K, 64, 2);
#pragma unroll
        for (int i = 0; i < ITERS; i++) {
            if (i < ITERS - 2)       cpwait<2>();
            else if (i == ITERS - 2) cpwait<1>();
            else                     cpwait<0>();
            __syncthreads();
            if (i + 3 < ITERS)
                prefetch(A, B, M, N, K, (i + 3) * 32, (i + 3) & 3);
            compute_stage(i & 3);
        }
    }

    __device__ __forceinline__ void store_f32(float* C, const float* resid, int N, int Mstore)
    {
        if ((row0 + warp_m * 32) >= Mstore) return;
#pragma unroll
        for (int i = 0; i < 2; i++)
#pragma unroll
            for (int j = 0; j < 4; j++) {
                size_t off = (size_t)(row0 + warp_m * 32 + i * 16) * N + col0 + warp_n * 64 + j * 16;
                if (resid) {
                    wmma::fragment<wmma::accumulator, 16, 16, 16, float> r;
                    wmma::load_matrix_sync(r, resid + off, N, wmma::mem_row_major);
#pragma unroll
                    for (int t = 0; t < r.num_elements; t++)
                        acc[i][j].x[t] += r.x[t];
                }
                wmma::store_matrix_sync(C + off, acc[i][j], N, wmma::mem_row_major);
            }
    }
};

// ---------------------------------------------------------------------------
// Value projection: 512 threads, tile 128x256 (FULL N -> value read once),
// A = f32 value with in-register bf16 conversion (distance-2 reg prefetch),
// B = g_wv via 4-stage cp.async. 16 warps (4x4), warp tile 32x64.
// Epilogue: bf16 HEAD-MAJOR scatter into g_vb.
// ---------------------------------------------------------------------------
#define BROW_V 264
#define B_STV (32 * BROW_V)
#define VAL_SMEM ((2 * A_ST + 4 * B_STV) * 2)   // 88064 bytes

__global__ __launch_bounds__(512, 1)
void gemm_value(const float* __restrict__ value, const float* __restrict__ brep)
{
    extern __shared__ char smc[];
    __nv_bfloat16* As  = (__nv_bfloat16*)smc;               // 2 stages
    __nv_bfloat16* Bsm = As + 2 * A_ST;                     // 4 stages

    const int tid = threadIdx.x;
    const int lane = tid & 31;
    const int wid = tid >> 5;
    const int warp_m = wid >> 2;      // 0..3
    const int warp_n = wid & 3;       // 0..3
    const int row0 = blockIdx.x * 128;

    wmma::fragment<wmma::accumulator, 16, 16, 16, float> acc[2][4];
#pragma unroll
    for (int i = 0; i < 2; i++)
#pragma unroll
        for (int j = 0; j < 4; j++)
            wmma::load_matrix_sync(acc[i][j],
                brep + warp_n * 64 + j * 16, 256, wmma::mem_row_major);

    // B prefetch: 32x256 per stage; 512 threads x 2 chunks of 16B
    auto prefetchB = [&](int k0, int st) {
#pragma unroll
        for (int it = 0; it < 2; it++) {
            int idx = tid + it * 512;       // 0..1023
            int k = idx >> 5, c = idx & 31;
            cp16(&Bsm[st * B_STV + k * BROW_V + c * 8],
                 g_wv + (size_t)(k0 + k) * 256 + c * 8, 16);
        }
        asm volatile("cp.async.commit_group;\n");
    };
    // A: thread t -> row t>>2, 8-float chunk (t&3); guard + convert
    const int arow = tid >> 2, acol = (tid & 3) * 8;
    auto ldgA = [&](int k0, uint2* r) {
        int gr = row0 + arow;
        if (gr < MV) {
            const float4* src = (const float4*)(value + (size_t)gr * 256 + k0 + acol);
            r[0] = pack4(src[0]);
            r[1] = pack4(src[1]);
        } else {
            r[0] = make_uint2(0u, 0u);
            r[1] = make_uint2(0u, 0u);
        }
    };
    auto stsA = [&](const uint2* r, int st) {
        uint4 w; w.x = r[0].x; w.y = r[0].y; w.z = r[1].x; w.w = r[1].y;
        *(uint4*)(As + st * A_ST + arow * AROW + acol) = w;
    };

    uint2 ar[2][2];
    ldgA(0,  ar[0]);
    ldgA(32, ar[1]);
    prefetchB(0,  0);
    prefetchB(32, 1);
    prefetchB(64, 2);

#pragma unroll
    for (int i = 0; i < 8; i++) {
        // stage (i&1) free: its readers (compute i-2) finished before the
        // barrier inside iteration i-1.
        stsA(ar[i & 1], i & 1);
        if (i + 2 < 8) ldgA((i + 2) * 32, ar[i & 1]);
        if (i + 3 < 8) prefetchB((i + 3) * 32, (i + 3) & 3);
        if (i < 6)      cpwait<3>();
        else if (i == 6) cpwait<1>();
        else             cpwait<0>();
        __syncthreads();
        {
            const __nv_bfloat16* as = As + (i & 1) * A_ST;
            const __nv_bfloat16* bs = Bsm + (i & 3) * B_STV;
#pragma unroll
            for (int kk = 0; kk < 2; kk++) {
                wmma::fragment<wmma::matrix_a, 16, 16, 16, __nv_bfloat16, wmma::row_major> a[2];
                wmma::fragment<wmma::matrix_b, 16, 16, 16, __nv_bfloat16, wmma::row_major> b[4];
#pragma unroll
                for (int ii = 0; ii < 2; ii++)
                    wmma::load_matrix_sync(a[ii], as + (warp_m * 32 + ii * 16) * AROW + kk * 16, AROW);
#pragma unroll
                for (int j = 0; j < 4; j++)
                    wmma::load_matrix_sync(b[j], bs + (kk * 16) * BROW_V + warp_n * 64 + j * 16, BROW_V);
#pragma unroll
                for (int ii = 0; ii < 2; ii++)
#pragma unroll
                    for (int j = 0; j < 4; j++)
                        wmma::mma_sync(acc[ii][j], a[ii], b[j], acc[ii][j]);
            }
        }
        __syncthreads();   // compute done before next iter's stsA overwrites
    }

    // bf16 head-major epilogue (per-warp 16x16 scratch)
    float* scratch = (float*)smc + wid * 256;
#pragma unroll
    for (int i = 0; i < 2; i++)
#pragma unroll
        for (int j = 0; j < 4; j++) {
            __syncwarp();
            wmma::store_matrix_sync(scratch, acc[i][j], 16, wmma::mem_row_major);
            __syncwarp();
            int r = lane >> 1, cb = (lane & 1) * 8;
            const float* sp = scratch + r * 16 + cb;
            float4 f0 = *(const float4*)sp;
            float4 f1 = *(const float4*)(sp + 4);
            uint2 lo = pack4(f0), hi = pack4(f1);
            uint4 o; o.x = lo.x; o.y = lo.y; o.z = hi.x; o.w = hi.y;
            int grow = row0 + warp_m * 32 + i * 16 + r;
            int gcol = warp_n * 64 + j * 16 + cb;
            size_t off = (size_t)(gcol >> 5) * (MV_PAD * HD) + (size_t)grow * HD + (gcol & 31);
            *(uint4*)(g_vb + off) = o;
        }
}

// ---------------------------------------------------------------------------
// Query projections (off + attn) in one flat launch; A = g_qb (bf16).
// ---------------------------------------------------------------------------
__global__ __launch_bounds__(256, 2)
void gemm_qproj(const float* __restrict__ brep)
{
    extern __shared__ char smc[];
    int t = blockIdx.x;

    const __nv_bfloat16* B;
    const float* brp;
    int N, row_t, col_t, prob;
    if (t < T_OFF) {
        prob = 0; B = g_wof; brp = brep + 4096;
        N = 256; row_t = t >> 1; col_t = t & 1;
    } else {
        int u = t - T_OFF;
        prob = 1; B = g_wat; brp = brep + 2 * 4096;
        N = 128; row_t = u; col_t = 0;
    }

    GemmCore g;
    g.init(smc, row_t * 128, col_t * 128, brp);
    g.mainloop<8>(g_qb, B, MQ, N, 256);

    if (prob == 0) g.store_f32(g_off, nullptr, 256, MQ_PAD);
    else           g.store_f32(g_aw,  nullptr, 128, MQ_PAD);
}

// ---------------------------------------------------------------------------
// Output projection + bias + fp32 residual (R11 path)
// ---------------------------------------------------------------------------
__global__ __launch_bounds__(256, 2)
void gemm_out(const float* __restrict__ brep, const float* __restrict__ query,
              float* __restrict__ out)
{
    extern __shared__ char smc[];
    GemmCore g;
    g.init(smc, blockIdx.y * 128, blockIdx.x * 128, brep + 3 * 4096);
    g.mainloop<8>(g_mid, g_wo, MQ, 256, 256);
    g.store_f32(out, query, 256, MQ);
}

// ---------------------------------------------------------------------------
// Fused sampling: TWO (b,q,h) units per warp (16 lanes each). R11 verbatim.
// ---------------------------------------------------------------------------
#define HSTRIDE (MV_PAD * HD)

__global__ __launch_bounds__(256)
void sample_fused(const float* __restrict__ refp)
{
    __shared__ int2 meta[16][66];

    const int warp = (blockIdx.x * blockDim.x + threadIdx.x) >> 5;
    const int lane = threadIdx.x & 31;
    const int half = lane >> 4;
    const int unit = warp * 2 + half;
    const int uloc = (threadIdx.x >> 5) * 2 + half;

    const int h  = unit & 7;
    const int bq = unit >> 3;
    const int b  = bq / NQ;

    {
        const int p = lane & 15;
        const float* awp = g_aw + bq * 128 + h * 16;
        float a = awp[p];
        float m = a;
#pragma unroll
        for (int o = 8; o; o >>= 1) m = fmaxf(m, __shfl_xor_sync(0xffffffffu, m, o));
        float e = __expf(a - m);
        float s = e;
#pragma unroll
        for (int o = 8; o; o >>= 1) s += __shfl_xor_sync(0xffffffffu, s, o);
        const float wp = e / s;

        const int l = p >> 2;
        const int W = (0x0D193264 >> (l * 8)) & 0xFF;               // 100,50,25,13
        const long long spack = 0LL | (10000LL << 14) | (12500LL << 28) | (13125LL << 42);
        const int START = (int)((spack >> (14 * l)) & 0x3FFF);      // 0,10000,12500,13125

        const float* offp = g_off + bq * 256 + h * 32;
        float rx = refp[bq * 8 + 2 * l];
        float ry = refp[bq * 8 + 2 * l + 1];

        float x = fmaf(rx, (float)W, offp[2 * p]) - 0.5f;
        float y = fmaf(ry, (float)W, offp[2 * p + 1]) - 0.5f;
        float xf = floorf(x), yf = floorf(y);
        int   x0 = (int)xf,  y0 = (int)yf;
        float wx1 = x - xf, wy1 = y - yf;
        float wx0 = 1.f - wx1, wy0 = 1.f - wy1;

        wx0 *= (float)(x0 >= 0 && x0 < W);
        wx1 *= (float)(x0 >= -1 && x0 < W - 1);
        wy0 *= (float)(y0 >= 0 && y0 < W);
        wy1 *= (float)(y0 >= -1 && y0 < W - 1);

        int xc0 = min(max(x0, 0), W - 1);
        int xc1 = min(max(x0 + 1, 0), W - 1);
        int yc0 = min(max(y0, 0), W - 1);
        int yc1 = min(max(y0 + 1, 0), W - 1);

        const int hb   = h * HSTRIDE;
        const int base = b * NV + START;
        int r0 = hb + (base + yc0 * W) * HD;
        int r1 = hb + (base + yc1 * W) * HD;

        int2* mp = &meta[uloc][p * 4];
        *(int4*)(mp)     = make_int4(r0 + xc0 * HD, __float_as_int(wp * wy0 * wx0),
                                     r0 + xc1 * HD, __float_as_int(wp * wy0 * wx1));
        *(int4*)(mp + 2) = make_int4(r1 + xc0 * HD, __float_as_int(wp * wy1 * wx0),
                                     r1 + xc1 * HD, __float_as_int(wp * wy1 * wx1));
    }
    __syncwarp();

    const int corner = (lane >> 2) & 3;
    const int sub    = lane & 3;
    const __nv_bfloat16* vbp = g_vb + sub * 8;
    const int2* mrow = &meta[uloc][corner];

    float a0 = 0.f, a1 = 0.f, a2 = 0.f, a3 = 0.f, a4 = 0.f, a5 = 0.f, a6 = 0.f, a7 = 0.f;
#pragma unroll
    for (int pt = 0; pt < 16; pt++) {
        int2 md = mrow[pt * 4];
        float w = __int_as_float(md.y);
        uint4 raw = *(const uint4*)(vbp + md.x);
        float2 f0 = __bfloat1622float2(*(__nv_bfloat162*)&raw.x);
        float2 f1 = __bfloat1622float2(*(__nv_bfloat162*)&raw.y);
        float2 f2 = __bfloat1622float2(*(__nv_bfloat162*)&raw.z);
        float2 f3 = __bfloat1622float2(*(__nv_bfloat162*)&raw.w);
        a0 = fmaf(w, f0.x, a0); a1 = fmaf(w, f0.y, a1);
        a2 = fmaf(w, f1.x, a2); a3 = fmaf(w, f1.y, a3);
        a4 = fmaf(w, f2.x, a4); a5 = fmaf(w, f2.y, a5);
        a6 = fmaf(w, f3.x, a6); a7 = fmaf(w, f3.y, a7);
    }
#pragma unroll
    for (int o = 4; o <= 8; o <<= 1) {
        a0 += __shfl_xor_sync(0xffffffffu, a0, o);
        a1 += __shfl_xor_sync(0xffffffffu, a1, o);
        a2 += __shfl_xor_sync(0xffffffffu, a2, o);
        a3 += __shfl_xor_sync(0xffffffffu, a3, o);
        a4 += __shfl_xor_sync(0xffffffffu, a4, o);
        a5 += __shfl_xor_sync(0xffffffffu, a5, o);
        a6 += __shfl_xor_sync(0xffffffffu, a6, o);
        a7 += __shfl_xor_sync(0xffffffffu, a7, o);
    }
    if (corner == 0) {
        __nv_bfloat162 t0 = __floats2bfloat162_rn(a0, a1);
        __nv_bfloat162 t1 = __floats2bfloat162_rn(a2, a3);
        __nv_bfloat162 t2 = __floats2bfloat162_rn(a4, a5);
        __nv_bfloat162 t3 = __floats2bfloat162_rn(a6, a7);
        uint4 o;
        o.x = *(uint32_t*)&t0; o.y = *(uint32_t*)&t1;
        o.z = *(uint32_t*)&t2; o.w = *(uint32_t*)&t3;
        *(uint4*)&g_mid[bq * 256 + h * HD + sub * 8] = o;
    }
}

// ---------------------------------------------------------------------------
extern "C" void kernel_launch(void* const* d_in, const int* in_sizes, int n_in,
                              void* d_out, int out_size)
{
    const float* query  = (const float*)d_in[0];
    const float* value  = (const float*)d_in[1];
    const float* refp   = (const float*)d_in[2];
    const float* W_off  = (const float*)d_in[3];
    const float* b_off  = (const float*)d_in[4];
    const float* W_attn = (const float*)d_in[5];
    const float* b_attn = (const float*)d_in[6];
    const float* W_val  = (const float*)d_in[7];
    const float* b_val  = (const float*)d_in[8];
    const float* W_out  = (const float*)d_in[9];
    const float* b_out  = (const float*)d_in[10];
    float* out = (float*)d_out;

    float* pbrep;
    cudaGetSymbolAddress((void**)&pbrep, g_brep);

    cudaFuncSetAttribute(gemm_value, cudaFuncAttributeMaxDynamicSharedMemorySize, VAL_SMEM);
    cudaFuncSetAttribute(gemm_qproj, cudaFuncAttributeMaxDynamicSharedMemorySize, GEMM_SMEM);
    cudaFuncSetAttribute(gemm_out,   cudaFuncAttributeMaxDynamicSharedMemorySize, GEMM_SMEM);

    // 0) query/weights bf16 conversion + bias tiles (value cvt fused into GEMM)
    cvt_all<<<(S_TOT + 255) / 256, 256>>>(query, W_val, W_off, W_attn, W_out,
                                          b_val, b_off, b_attn, b_out);

    // 1) value projection: f32 A read once, converted in-flight, head-major bf16 out
    gemm_value<<<T_VALV, 512, VAL_SMEM>>>(value, pbrep);

    // 2) offset + attention projections (bf16 A)
    gemm_qproj<<<T_QP, 256, GEMM_SMEM>>>(pbrep);

    // 3) fused sampler: 2 units/warp, head-major gather
    sample_fused<<<(MQ * NH) / 16, 256>>>(refp);

    // 4) output projection + bias + fp32 residual
    gemm_out<<<dim3(2, MQ_PAD / 128), 256, GEMM_SMEM>>>(pbrep, query, out);
}